// round 6
// baseline (speedup 1.0000x reference)
#include <cuda_runtime.h>
#include <cuda_bf16.h>
#include <math.h>
#include <stdint.h>

#define D 768
#define MAXN 50000
#define MAXE 100000

// ---------------- scratch (__device__ globals; no allocations allowed) ------
__device__ float  g_e[(size_t)512 * D];        // bond-type table (512 rows)
__device__ float  g_u[(size_t)MAXN * D];       // t / u fp32
__device__ float  g_agg[(size_t)MAXN * D];     // h + scatter sum
__device__ int    g_etype[MAXE];
__device__ int8_t g_aq1[(size_t)MAXN * D];     // A-operand slice 1
__device__ int8_t g_aq2[(size_t)MAXN * D];     // A-operand slice 2
__device__ float  g_ars[MAXN];                 // A row scales
__device__ int8_t g_tq1[(size_t)MAXN * D];     // t slices
__device__ int8_t g_tq2[(size_t)MAXN * D];
__device__ float  g_trs[MAXN];
__device__ int8_t g_wq1[(size_t)12 * D * D];   // W^T slices [z][n][k]
__device__ int8_t g_wq2[(size_t)12 * D * D];
__device__ float  g_ws[12 * D];                // W col scales [z][n]

__device__ __forceinline__ float gelu_f(float x) {
    float x3 = x * x * x;
    return 0.5f * x * (1.0f + tanhf(0.7978845608028654f * (x + 0.044715f * x3)));
}
__device__ __forceinline__ uint32_t smem_u32(const void* p) {
    uint32_t a;
    asm("{ .reg .u64 t; cvta.to.shared.u64 t, %1; cvt.u32.u64 %0, t; }" : "=r"(a) : "l"(p));
    return a;
}
__device__ __forceinline__ uint32_t sw64(uint32_t off) { return off ^ ((off >> 3) & 0x30); }

__device__ __forceinline__ void ldm_x4(uint32_t* r, uint32_t a) {
    asm volatile("ldmatrix.sync.aligned.m8n8.x4.shared.b16 {%0,%1,%2,%3}, [%4];"
        : "=r"(r[0]), "=r"(r[1]), "=r"(r[2]), "=r"(r[3]) : "r"(a));
}
__device__ __forceinline__ void mma_s8(int* c, const uint32_t* a, const uint32_t* b) {
    asm volatile("mma.sync.aligned.m16n8k32.row.col.s32.s8.s8.s32 "
        "{%0,%1,%2,%3},{%4,%5,%6,%7},{%8,%9},{%0,%1,%2,%3};"
        : "+r"(c[0]), "+r"(c[1]), "+r"(c[2]), "+r"(c[3])
        : "r"(a[0]), "r"(a[1]), "r"(a[2]), "r"(a[3]), "r"(b[0]), "r"(b[1]));
}
// 2-slice quantization: v ~ rs*(q1 + q2/254), rs = rowmax/124
__device__ __forceinline__ void quant2(float v, float c1, int8_t& o1, int8_t& o2) {
    float s = v * c1;
    int q1 = __float2int_rn(s);
    int q2 = __float2int_rn((s - (float)q1) * 254.f);
    o1 = (int8_t)q1;
    o2 = (int8_t)q2;
}

// ---------------------------------------------------------------------------
// Weight quantization: wq[z][n][k] = slices of W_z[k][n]; ws[z][n] = row scale.
// One block per (n, z); threads stride k (column gather, one-time cost).
// ---------------------------------------------------------------------------
__global__ void w_quant(const float* __restrict__ aw1, const float* __restrict__ aw2,
                        const float* __restrict__ bw1, const float* __restrict__ bw2,
                        const float* __restrict__ cw1, const float* __restrict__ cw2,
                        int8_t* __restrict__ q1o, int8_t* __restrict__ q2o,
                        float* __restrict__ wso)
{
    int n = blockIdx.x, z = blockIdx.y;
    const float* W;
    if      (z == 0) W = aw1;
    else if (z == 1) W = aw2;
    else if (z == 2) W = bw1;
    else if (z == 3) W = bw2;
    else if (z < 8)  W = cw1 + (size_t)(z - 4) * D * D;
    else             W = cw2 + (size_t)(z - 8) * D * D;

    __shared__ float sred[8];
    __shared__ float sc1;
    int tid = threadIdx.x;
    float v[3], mx = 0.f;
    #pragma unroll
    for (int t = 0; t < 3; t++) {
        int k = tid + t * 256;
        v[t] = W[(size_t)k * D + n];
        mx = fmaxf(mx, fabsf(v[t]));
    }
    #pragma unroll
    for (int off = 16; off; off >>= 1)
        mx = fmaxf(mx, __shfl_down_sync(0xffffffffu, mx, off));
    if ((tid & 31) == 0) sred[tid >> 5] = mx;
    __syncthreads();
    if (tid == 0) {
        float m = 0.f;
        #pragma unroll
        for (int i = 0; i < 8; i++) m = fmaxf(m, sred[i]);
        sc1 = 124.f / fmaxf(m, 1e-30f);
        wso[z * D + n] = m * (1.f / 124.f);
    }
    __syncthreads();
    float c1 = sc1;
    #pragma unroll
    for (int t = 0; t < 3; t++) {
        int k = tid + t * 256;
        size_t o = (size_t)z * D * D + (size_t)n * D + k;
        quant2(v[t], c1, q1o[o], q2o[o]);
    }
}

// ---------------------------------------------------------------------------
// Row quantization of an fp32 matrix -> 2 int8 slices + row scale.
// ---------------------------------------------------------------------------
__global__ void quant_rows(const float* __restrict__ in,
                           int8_t* __restrict__ q1o, int8_t* __restrict__ q2o,
                           float* __restrict__ rso, int M)
{
    int row = blockIdx.x;
    if (row >= M) return;
    __shared__ float sred[8];
    __shared__ float sc1;
    int tid = threadIdx.x;
    float v[3], mx = 0.f;
    #pragma unroll
    for (int t = 0; t < 3; t++) {
        v[t] = in[(size_t)row * D + tid + t * 256];
        mx = fmaxf(mx, fabsf(v[t]));
    }
    #pragma unroll
    for (int off = 16; off; off >>= 1)
        mx = fmaxf(mx, __shfl_down_sync(0xffffffffu, mx, off));
    if ((tid & 31) == 0) sred[tid >> 5] = mx;
    __syncthreads();
    if (tid == 0) {
        float m = 0.f;
        #pragma unroll
        for (int i = 0; i < 8; i++) m = fmaxf(m, sred[i]);
        sc1 = 124.f / fmaxf(m, 1e-30f);
        rso[row] = m * (1.f / 124.f);
    }
    __syncthreads();
    float c1 = sc1;
    #pragma unroll
    for (int t = 0; t < 3; t++) {
        size_t o = (size_t)row * D + tid + t * 256;
        quant2(v[t], c1, q1o[o], q2o[o]);
    }
}

// ---------------------------------------------------------------------------
// IMMA 2-slice GEMM.  CTA tile 64x128, BK=64 int8, 4-stage cp.async,
// 8 warps 32x32, 2 CTAs/SM.  C = epi( A@W + bias ) dequantized.
// EPI: 0 none / 1 relu / 2 gelu.  OUT: 0 -> C; 2 -> C and C2 (dup).
// Stage: Aq1 4K | Aq2 4K | Bq1 8K | Bq2 8K = 24K.
// ---------------------------------------------------------------------------
#define STG_BYTES 24576
#define NSTAGE 4
#define NITER  12
#define GEMM_SMEM (NSTAGE * STG_BYTES + 1024)

template <int EPI, int OUT>
__global__ __launch_bounds__(256, 2) void gemm_imma(
    const int8_t* __restrict__ Aq1, const int8_t* __restrict__ Aq2,
    const float* __restrict__ Ars,
    const int8_t* __restrict__ Bq1, const int8_t* __restrict__ Bq2,
    const float* __restrict__ Bcs,
    const float* __restrict__ bias, float* __restrict__ C,
    float* __restrict__ C2, int M)
{
    extern __shared__ char dsm[];
    uint32_t raw  = smem_u32(dsm);
    uint32_t base = (raw + 1023u) & ~1023u;

    const int tid  = threadIdx.x;
    const int lane = tid & 31, wid = tid >> 5;
    const int bm = blockIdx.y * 64, bn = blockIdx.x * 128;
    const int warp_m = (wid & 1) * 32, warp_n = (wid >> 1) * 32;

    int acc1[2][4][4], acc2[2][4][4];
    #pragma unroll
    for (int i = 0; i < 2; i++)
        #pragma unroll
        for (int j = 0; j < 4; j++)
            #pragma unroll
            for (int q = 0; q < 4; q++) { acc1[i][j][q] = 0; acc2[i][j][q] = 0; }

    auto prefetch = [&](int c) {
        uint32_t sb = base + (uint32_t)(c & (NSTAGE - 1)) * STG_BYTES;
        int k0 = c * 64;
        #pragma unroll
        for (int r = 0; r < 6; r++) {
            int u = tid + r * 256;                 // 0..1535 (16B chunks)
            const int8_t* gp;
            uint32_t so;
            int nb = 16;
            if (u < 512) {                          // A: q1(256) q2(256)
                int mat = u >> 8, idx = u & 255;
                int row = idx >> 2, c16 = idx & 3;
                so = sb + (uint32_t)mat * 4096u + sw64((uint32_t)(row * 64 + c16 * 16));
                int grow = bm + row;
                int cl = (grow < M) ? grow : 0;
                if (grow >= M) nb = 0;
                gp = (mat == 0 ? Aq1 : Aq2) + (size_t)cl * D + k0 + c16 * 16;
            } else {                                // B: q1(512) q2(512)
                int v = u - 512;
                int mat = v >> 9, idx = v & 511;
                int row = idx >> 2, c16 = idx & 3;
                so = sb + 8192u + (uint32_t)mat * 8192u
                   + sw64((uint32_t)(row * 64 + c16 * 16));
                gp = (mat == 0 ? Bq1 : Bq2) + (size_t)(bn + row) * D + k0 + c16 * 16;
            }
            asm volatile("cp.async.cg.shared.global [%0], [%1], 16, %2;"
                         :: "r"(so), "l"(gp), "r"(nb));
        }
        asm volatile("cp.async.commit_group;" ::: "memory");
    };

    prefetch(0);
    prefetch(1);
    prefetch(2);

    const uint32_t aRB = (uint32_t)((warp_m + (lane & 15)) * 64 + (lane >> 4) * 16);
    const uint32_t bRB = (uint32_t)((warp_n + (lane & 7) + ((lane >> 4) << 3)) * 64
                                    + ((lane >> 3) & 1) * 16);

    for (int c = 0; c < NITER; c++) {
        if      (c < NITER - 2)  asm volatile("cp.async.wait_group 2;" ::: "memory");
        else if (c == NITER - 2) asm volatile("cp.async.wait_group 1;" ::: "memory");
        else                     asm volatile("cp.async.wait_group 0;" ::: "memory");
        __syncthreads();
        if (c + 3 < NITER) prefetch(c + 3);   // writes stage (c-1)%4: consumed pre-sync

        uint32_t sb = base + (uint32_t)(c & (NSTAGE - 1)) * STG_BYTES;
        #pragma unroll
        for (int ks = 0; ks < 2; ks++) {       // each ks = 32 int8 of K
            uint32_t a1[2][4], a2[2][4], b1[4][2], b2[4][2];
            #pragma unroll
            for (int mf = 0; mf < 2; mf++) {
                uint32_t off = aRB + mf * 1024 + ks * 32;
                ldm_x4(a1[mf], sb + sw64(off));
                ldm_x4(a2[mf], sb + 4096u + sw64(off));
            }
            #pragma unroll
            for (int n2 = 0; n2 < 2; n2++) {
                uint32_t off = bRB + n2 * 1024 + ks * 32;
                uint32_t t[4];
                ldm_x4(t, sb + 8192u + sw64(off));
                b1[n2 * 2][0] = t[0]; b1[n2 * 2][1] = t[1];
                b1[n2 * 2 + 1][0] = t[2]; b1[n2 * 2 + 1][1] = t[3];
                ldm_x4(t, sb + 16384u + sw64(off));
                b2[n2 * 2][0] = t[0]; b2[n2 * 2][1] = t[1];
                b2[n2 * 2 + 1][0] = t[2]; b2[n2 * 2 + 1][1] = t[3];
            }
            #pragma unroll
            for (int mf = 0; mf < 2; mf++)
                #pragma unroll
                for (int nf = 0; nf < 4; nf++) {
                    mma_s8(acc1[mf][nf], a1[mf], b1[nf]);
                    mma_s8(acc2[mf][nf], a1[mf], b2[nf]);
                    mma_s8(acc2[mf][nf], a2[mf], b1[nf]);
                }
        }
    }

    // ---- epilogue: dequant + bias + activation ------------------------------
    const int grp = lane >> 2, tig = lane & 3;
    #pragma unroll
    for (int mf = 0; mf < 2; mf++) {
        #pragma unroll
        for (int h2 = 0; h2 < 2; h2++) {
            int row = bm + warp_m + mf * 16 + grp + h2 * 8;
            if (row >= M) continue;
            float rsm = __ldg(&Ars[row]);
            #pragma unroll
            for (int nf = 0; nf < 4; nf++) {
                int col = bn + warp_n + nf * 8 + tig * 2;
                float s0 = (float)acc1[mf][nf][h2 * 2 + 0]
                         + (float)acc2[mf][nf][h2 * 2 + 0] * (1.f / 254.f);
                float s1 = (float)acc1[mf][nf][h2 * 2 + 1]
                         + (float)acc2[mf][nf][h2 * 2 + 1] * (1.f / 254.f);
                float v0 = s0 * rsm * __ldg(&Bcs[col])     + __ldg(&bias[col]);
                float v1 = s1 * rsm * __ldg(&Bcs[col + 1]) + __ldg(&bias[col + 1]);
                if (EPI == 1) { v0 = fmaxf(v0, 0.f); v1 = fmaxf(v1, 0.f); }
                else if (EPI == 2) { v0 = gelu_f(v0); v1 = gelu_f(v1); }
                *(float2*)(C + (size_t)row * D + col) = make_float2(v0, v1);
                if (OUT == 2)
                    *(float2*)(C2 + (size_t)row * D + col) = make_float2(v0, v1);
            }
        }
    }
}

// ---------------------------------------------------------------------------
// Fused embedding-sum + LayerNorm -> 2-slice int8 + row scale.
// ids == nullptr -> synthesize ids from row index (bond table 8x8x8).
// ---------------------------------------------------------------------------
__global__ void encode_embed_ln(const int* __restrict__ ids, int F, int V,
                                const float* __restrict__ emb,
                                const float* __restrict__ g,
                                const float* __restrict__ b,
                                int8_t* __restrict__ q1o, int8_t* __restrict__ q2o,
                                float* __restrict__ rso, int M)
{
    int row = blockIdx.x;
    if (row >= M) return;
    __shared__ int   sid[16];
    __shared__ float sred[2][8];
    __shared__ float smv[3];
    int tid = threadIdx.x;
    if (ids) {
        if (tid < F) sid[tid] = ids[(size_t)row * F + tid];
    } else if (tid == 0) {
        sid[0] = row >> 6; sid[1] = (row >> 3) & 7; sid[2] = row & 7;
    }
    __syncthreads();

    float v[3];
    float s = 0.f, q = 0.f;
    #pragma unroll
    for (int t = 0; t < 3; t++) {
        int c = tid + t * 256;
        float acc = 0.f;
        for (int f = 0; f < F; f++)
            acc += emb[((size_t)f * V + sid[f]) * D + c];
        v[t] = acc;
        s += acc;
        q += acc * acc;
    }
    #pragma unroll
    for (int off = 16; off; off >>= 1) {
        s += __shfl_down_sync(0xffffffffu, s, off);
        q += __shfl_down_sync(0xffffffffu, q, off);
    }
    int wid = tid >> 5, lane = tid & 31;
    if (lane == 0) { sred[0][wid] = s; sred[1][wid] = q; }
    __syncthreads();
    if (tid == 0) {
        float ss = 0.f, qq = 0.f;
        #pragma unroll
        for (int i = 0; i < 8; i++) { ss += sred[0][i]; qq += sred[1][i]; }
        float mean = ss * (1.0f / D);
        float var  = qq * (1.0f / D) - mean * mean;
        smv[0] = mean;
        smv[1] = rsqrtf(var + 1e-5f);
    }
    __syncthreads();
    float mean = smv[0], rstd = smv[1];
    float mx = 0.f;
    #pragma unroll
    for (int t = 0; t < 3; t++) {
        int c = tid + t * 256;
        v[t] = (v[t] - mean) * rstd * g[c] + b[c];
        mx = fmaxf(mx, fabsf(v[t]));
    }
    #pragma unroll
    for (int off = 16; off; off >>= 1)
        mx = fmaxf(mx, __shfl_down_sync(0xffffffffu, mx, off));
    if (lane == 0) sred[0][wid] = mx;
    __syncthreads();
    if (tid == 0) {
        float m = 0.f;
        #pragma unroll
        for (int i = 0; i < 8; i++) m = fmaxf(m, sred[0][i]);
        smv[2] = 124.f / fmaxf(m, 1e-30f);
        rso[row] = m * (1.f / 124.f);
    }
    __syncthreads();
    float c1 = smv[2];
    #pragma unroll
    for (int t = 0; t < 3; t++) {
        size_t o = (size_t)row * D + tid + t * 256;
        quant2(v[t], c1, q1o[o], q2o[o]);
    }
}

// ---------------------------------------------------------------------------
// Per-edge bond type index
// ---------------------------------------------------------------------------
__global__ void etype_k(const int* __restrict__ ea, int* __restrict__ et, int E)
{
    int i = blockIdx.x * blockDim.x + threadIdx.x;
    if (i >= E) return;
    et[i] = ea[i * 3] * 64 + ea[i * 3 + 1] * 8 + ea[i * 3 + 2];
}

// ---------------------------------------------------------------------------
// Fused gelu + residual + LayerNorm; writes h AND agg (= next layer's z-base).
// ---------------------------------------------------------------------------
__global__ void gelu_res_ln(const float* __restrict__ u, float* __restrict__ h,
                            float* __restrict__ agg,
                            const float* __restrict__ g,
                            const float* __restrict__ b, int M)
{
    int row = blockIdx.x;
    if (row >= M) return;
    __shared__ float sred[2][8];
    __shared__ float smv[2];
    int tid = threadIdx.x;

    float v[3];
    float s = 0.f, q = 0.f;
    #pragma unroll
    for (int t = 0; t < 3; t++) {
        int c = tid + t * 256;
        float val = gelu_f(u[(size_t)row * D + c]) + h[(size_t)row * D + c];
        v[t] = val;
        s += val;
        q += val * val;
    }
    #pragma unroll
    for (int off = 16; off; off >>= 1) {
        s += __shfl_down_sync(0xffffffffu, s, off);
        q += __shfl_down_sync(0xffffffffu, q, off);
    }
    int wid = tid >> 5, lane = tid & 31;
    if (lane == 0) { sred[0][wid] = s; sred[1][wid] = q; }
    __syncthreads();
    if (tid == 0) {
        float ss = 0.f, qq = 0.f;
        #pragma unroll
        for (int i = 0; i < 8; i++) { ss += sred[0][i]; qq += sred[1][i]; }
        float mean = ss * (1.0f / D);
        float var  = qq * (1.0f / D) - mean * mean;
        smv[0] = mean;
        smv[1] = rsqrtf(var + 1e-5f);
    }
    __syncthreads();
    float mean = smv[0], rstd = smv[1];
    #pragma unroll
    for (int t = 0; t < 3; t++) {
        int c = tid + t * 256;
        float val = (v[t] - mean) * rstd * g[c] + b[c];
        h[(size_t)row * D + c] = val;
        agg[(size_t)row * D + c] = val;
    }
}

// ---------------------------------------------------------------------------
// Edge message + scatter: agg += relu(h[src] + etab[etype])  (agg pre-init = h)
// ---------------------------------------------------------------------------
__global__ void edge_scatter(const float* __restrict__ h,
                             const float* __restrict__ etab,
                             const int* __restrict__ et,
                             const int* __restrict__ src,
                             const int* __restrict__ dst,
                             float* __restrict__ agg, int E)
{
    long long i = (long long)blockIdx.x * blockDim.x + threadIdx.x;
    long long total = (long long)E * (D / 4);
    if (i >= total) return;
    int eid = (int)(i / (D / 4));
    int c   = (int)(i % (D / 4)) * 4;
    int sN  = __ldg(&src[eid]);
    int dN  = __ldg(&dst[eid]);
    int ty  = __ldg(&et[eid]);
    float4 hv = *(const float4*)(h + (size_t)sN * D + c);
    float4 ev = *(const float4*)(etab + (size_t)ty * D + c);
    float m0 = fmaxf(hv.x + ev.x, 0.f);
    float m1 = fmaxf(hv.y + ev.y, 0.f);
    float m2 = fmaxf(hv.z + ev.z, 0.f);
    float m3 = fmaxf(hv.w + ev.w, 0.f);
    float* p = agg + (size_t)dN * D + c;
    asm volatile("red.global.add.v4.f32 [%0], {%1, %2, %3, %4};"
                 :: "l"(p), "f"(m0), "f"(m1), "f"(m2), "f"(m3) : "memory");
}

// ---------------------------------------------------------------------------
extern "C" void kernel_launch(void* const* d_in, const int* in_sizes, int n_in,
                              void* d_out, int out_size)
{
    const int*   x         = (const int*)d_in[0];
    const int*   edge_attr = (const int*)d_in[1];
    const int*   edge_index= (const int*)d_in[2];
    const float* atom_emb  = (const float*)d_in[3];
    const float* atom_ln_g = (const float*)d_in[4];
    const float* atom_ln_b = (const float*)d_in[5];
    const float* atom_w1   = (const float*)d_in[6];
    const float* atom_b1   = (const float*)d_in[7];
    const float* atom_w2   = (const float*)d_in[8];
    const float* atom_b2   = (const float*)d_in[9];
    const float* bond_emb  = (const float*)d_in[10];
    const float* bond_ln_g = (const float*)d_in[11];
    const float* bond_ln_b = (const float*)d_in[12];
    const float* bond_w1   = (const float*)d_in[13];
    const float* bond_b1   = (const float*)d_in[14];
    const float* bond_w2   = (const float*)d_in[15];
    const float* bond_b2   = (const float*)d_in[16];
    const float* conv_w1   = (const float*)d_in[17];
    const float* conv_b1   = (const float*)d_in[18];
    const float* conv_w2   = (const float*)d_in[19];
    const float* conv_b2   = (const float*)d_in[20];
    const float* ln_g      = (const float*)d_in[21];
    const float* ln_b      = (const float*)d_in[22];

    int N = in_sizes[0] / 9;
    int E = in_sizes[1] / 3;
    const int* src = edge_index;
    const int* dst = edge_index + E;
    float* h = (float*)d_out;

    float *etab, *u, *agg, *ars, *trs, *ws;
    int* et;
    int8_t *aq1, *aq2, *tq1, *tq2, *wq1, *wq2;
    cudaGetSymbolAddress((void**)&etab, g_e);
    cudaGetSymbolAddress((void**)&u,    g_u);
    cudaGetSymbolAddress((void**)&agg,  g_agg);
    cudaGetSymbolAddress((void**)&et,   g_etype);
    cudaGetSymbolAddress((void**)&aq1,  g_aq1);
    cudaGetSymbolAddress((void**)&aq2,  g_aq2);
    cudaGetSymbolAddress((void**)&ars,  g_ars);
    cudaGetSymbolAddress((void**)&tq1,  g_tq1);
    cudaGetSymbolAddress((void**)&tq2,  g_tq2);
    cudaGetSymbolAddress((void**)&trs,  g_trs);
    cudaGetSymbolAddress((void**)&wq1,  g_wq1);
    cudaGetSymbolAddress((void**)&wq2,  g_wq2);
    cudaGetSymbolAddress((void**)&ws,   g_ws);

    cudaFuncSetAttribute(gemm_imma<2, 0>, cudaFuncAttributeMaxDynamicSharedMemorySize, GEMM_SMEM);
    cudaFuncSetAttribute(gemm_imma<1, 0>, cudaFuncAttributeMaxDynamicSharedMemorySize, GEMM_SMEM);
    cudaFuncSetAttribute(gemm_imma<0, 0>, cudaFuncAttributeMaxDynamicSharedMemorySize, GEMM_SMEM);
    cudaFuncSetAttribute(gemm_imma<0, 2>, cudaFuncAttributeMaxDynamicSharedMemorySize, GEMM_SMEM);

    const size_t WSZ = (size_t)D * D;

    // one-time weight quantization (12 matrices)
    w_quant<<<dim3(D, 12), 256>>>(atom_w1, atom_w2, bond_w1, bond_w2,
                                  conv_w1, conv_w2, wq1, wq2, ws);
    etype_k<<<(E + 255) / 256, 256>>>(edge_attr, et, E);

    dim3 gN(6, (N + 63) / 64);
    dim3 gT(6, 8);

    // --- Bond-type table (512 rows) -> etab ---
    encode_embed_ln<<<512, 256>>>(nullptr, 3, 8, bond_emb, bond_ln_g, bond_ln_b,
                                  aq1, aq2, ars, 512);
    gemm_imma<2, 0><<<gT, 256, GEMM_SMEM>>>(aq1, aq2, ars, wq1 + 2 * WSZ, wq2 + 2 * WSZ,
                                            ws + 2 * D, bond_b1, u, nullptr, 512);
    quant_rows<<<512, 256>>>(u, tq1, tq2, trs, 512);
    gemm_imma<0, 0><<<gT, 256, GEMM_SMEM>>>(tq1, tq2, trs, wq1 + 3 * WSZ, wq2 + 3 * WSZ,
                                            ws + 3 * D, bond_b2, etab, nullptr, 512);

    // --- Atom encoder -> h, agg ---
    encode_embed_ln<<<N, 256>>>(x, 9, 128, atom_emb, atom_ln_g, atom_ln_b,
                                aq1, aq2, ars, N);
    gemm_imma<2, 0><<<gN, 256, GEMM_SMEM>>>(aq1, aq2, ars, wq1 + 0 * WSZ, wq2 + 0 * WSZ,
                                            ws + 0 * D, atom_b1, u, nullptr, N);
    quant_rows<<<N, 256>>>(u, tq1, tq2, trs, N);
    gemm_imma<0, 2><<<gN, 256, GEMM_SMEM>>>(tq1, tq2, trs, wq1 + 1 * WSZ, wq2 + 1 * WSZ,
                                            ws + 1 * D, atom_b2, h, agg, N);

    // --- 4 GINE layers ---
    long long totE = (long long)E * (D / 4);
    int edgeBlocks = (int)((totE + 255) / 256);
    for (int l = 0; l < 4; l++) {
        edge_scatter<<<edgeBlocks, 256>>>(h, etab, et, src, dst, agg, E);
        quant_rows<<<N, 256>>>(agg, aq1, aq2, ars, N);
        gemm_imma<1, 0><<<gN, 256, GEMM_SMEM>>>(aq1, aq2, ars,
                                                wq1 + (size_t)(4 + l) * WSZ, wq2 + (size_t)(4 + l) * WSZ,
                                                ws + (4 + l) * D, conv_b1 + (size_t)l * D,
                                                u, nullptr, N);
        quant_rows<<<N, 256>>>(u, tq1, tq2, trs, N);
        gemm_imma<0, 0><<<gN, 256, GEMM_SMEM>>>(tq1, tq2, trs,
                                                wq1 + (size_t)(8 + l) * WSZ, wq2 + (size_t)(8 + l) * WSZ,
                                                ws + (8 + l) * D, conv_b2 + (size_t)l * D,
                                                u, nullptr, N);
        gelu_res_ln<<<N, 256>>>(u, h, agg, ln_g + (size_t)l * D, ln_b + (size_t)l * D, N);
    }
}

// round 7
// speedup vs baseline: 2.3455x; 2.3455x over previous
#include <cuda_runtime.h>
#include <cuda_bf16.h>
#include <math.h>
#include <stdint.h>

#define D 768
#define MAXN 50000
#define MAXE 100000

typedef __nv_bfloat16 bf16;

// ---------------- scratch (__device__ globals; no allocations allowed) ------
__device__ float g_e[(size_t)512 * D];        // bond-type table (512 rows)
__device__ float g_u[(size_t)MAXN * D];       // layer MLP output (fp32)
__device__ float g_agg[(size_t)MAXN * D];     // h + scatter-add accumulator
__device__ int   g_etype[MAXE];
__device__ bf16  g_s0h[(size_t)MAXN * D];     // GEMM1 input, split hi
__device__ bf16  g_s0l[(size_t)MAXN * D];     //                    lo
__device__ bf16  g_s1h[(size_t)MAXN * D];     // GEMM2 input, split hi
__device__ bf16  g_s1l[(size_t)MAXN * D];     //                    lo
__device__ bf16  g_wthi[(size_t)12 * D * D];  // W^T split hi  [z][n][k]
__device__ bf16  g_wtlo[(size_t)12 * D * D];  // W^T split lo

__device__ __forceinline__ float gelu_f(float x) {
    float x3 = x * x * x;
    return 0.5f * x * (1.0f + tanhf(0.7978845608028654f * (x + 0.044715f * x3)));
}
__device__ __forceinline__ uint32_t smem_u32(const void* p) {
    uint32_t a;
    asm("{ .reg .u64 t; cvta.to.shared.u64 t, %1; cvt.u32.u64 %0, t; }" : "=r"(a) : "l"(p));
    return a;
}
__device__ __forceinline__ uint32_t sw64(uint32_t off) { return off ^ ((off >> 3) & 0x30); }

__device__ __forceinline__ void ldm_x4(uint32_t* r, uint32_t a) {
    asm volatile("ldmatrix.sync.aligned.m8n8.x4.shared.b16 {%0,%1,%2,%3}, [%4];"
        : "=r"(r[0]), "=r"(r[1]), "=r"(r[2]), "=r"(r[3]) : "r"(a));
}
__device__ __forceinline__ void mma_bf16(float* c, const uint32_t* a, const uint32_t* b) {
    asm volatile("mma.sync.aligned.m16n8k16.row.col.f32.bf16.bf16.f32 "
        "{%0,%1,%2,%3},{%4,%5,%6,%7},{%8,%9},{%0,%1,%2,%3};"
        : "+f"(c[0]), "+f"(c[1]), "+f"(c[2]), "+f"(c[3])
        : "r"(a[0]), "r"(a[1]), "r"(a[2]), "r"(a[3]), "r"(b[0]), "r"(b[1]));
}

// ---------------------------------------------------------------------------
// W transpose + bf16 split:  Wt_hi/lo[z][n][k] = split(W_z[k][n])
// ---------------------------------------------------------------------------
__global__ void split_transpose_w(const float* __restrict__ aw1, const float* __restrict__ aw2,
                                  const float* __restrict__ bw1, const float* __restrict__ bw2,
                                  const float* __restrict__ cw1, const float* __restrict__ cw2,
                                  bf16* __restrict__ hi, bf16* __restrict__ lo)
{
    __shared__ float t[32][33];
    int z = blockIdx.z;
    const float* W;
    if      (z == 0) W = aw1;
    else if (z == 1) W = aw2;
    else if (z == 2) W = bw1;
    else if (z == 3) W = bw2;
    else if (z < 8)  W = cw1 + (size_t)(z - 4) * D * D;
    else             W = cw2 + (size_t)(z - 8) * D * D;

    int n0 = blockIdx.x * 32, k0 = blockIdx.y * 32;
    int tx = threadIdx.x, ty = threadIdx.y;     // (32, 8)
    #pragma unroll
    for (int i = 0; i < 4; i++)
        t[ty + i * 8][tx] = W[(size_t)(k0 + ty + i * 8) * D + n0 + tx];
    __syncthreads();
    #pragma unroll
    for (int i = 0; i < 4; i++) {
        float v = t[tx][ty + i * 8];
        bf16 h = __float2bfloat16_rn(v);
        bf16 l = __float2bfloat16_rn(v - __bfloat162float(h));
        size_t o = (size_t)z * D * D + (size_t)(n0 + ty + i * 8) * D + (k0 + tx);
        hi[o] = h;
        lo[o] = l;
    }
}

// ---------------------------------------------------------------------------
// HMMA bf16x3-split GEMM.  CTA tile 128x128, BK=32, 3-stage cp.async,
// single sync/iter, 8 warps 64x32, 2 CTAs/SM.
// EPI: 0 none / 1 relu / 2 gelu.
// OUT: 0 fp32 C / 1 split (Ch, Cl) / 2 fp32 C and C2.
// Stage: Ah 8K | Al 8K | Bh 8K | Bl 8K = 32K.
// ---------------------------------------------------------------------------
#define STG_BYTES 32768
#define NSTAGE 3
#define NITER  24
#define GEMM_SMEM (NSTAGE * STG_BYTES + 1024)

template <int EPI, int OUT>
__global__ __launch_bounds__(256, 2) void gemm_mma(
    const bf16* __restrict__ Ah_, const bf16* __restrict__ Al_,
    const bf16* __restrict__ Bh_, const bf16* __restrict__ Bl_,
    const float* __restrict__ bias, float* __restrict__ C,
    bf16* __restrict__ Ch, bf16* __restrict__ Cl, float* __restrict__ C2, int M)
{
    extern __shared__ char dsm[];
    uint32_t raw  = smem_u32(dsm);
    uint32_t base = (raw + 1023u) & ~1023u;

    const int tid  = threadIdx.x;
    const int lane = tid & 31, wid = tid >> 5;
    const int bm = blockIdx.y * 128, bn = blockIdx.x * 128;
    const int warp_m = (wid & 1) * 64, warp_n = (wid >> 1) * 32;

    float acc[4][4][4];
    #pragma unroll
    for (int i = 0; i < 4; i++)
        #pragma unroll
        for (int j = 0; j < 4; j++)
            #pragma unroll
            for (int q = 0; q < 4; q++) acc[i][j][q] = 0.f;

    auto prefetch = [&](int c) {
        uint32_t sb = base + (uint32_t)(c % NSTAGE) * STG_BYTES;
        int k0 = c * 32;
        #pragma unroll
        for (int r = 0; r < 8; r++) {
            int u = tid + r * 256;                 // 0..2047 (16B chunks)
            const bf16* gp;
            uint32_t so;
            int nb = 16;
            if (u < 1024) {                         // A: Ah(512) Al(512)
                int mat = u >> 9, idx = u & 511;
                int row = idx >> 2, c16 = idx & 3;  // row 0..127, c16 0..3
                so = sb + (uint32_t)mat * 8192u + sw64((uint32_t)(row * 64 + c16 * 16));
                int grow = bm + row;
                int cl = (grow < M) ? grow : 0;
                if (grow >= M) nb = 0;
                gp = (mat == 0 ? Ah_ : Al_) + (size_t)cl * D + k0 + c16 * 8;
            } else {                                // B: Bh(512) Bl(512)
                int v = u - 1024;
                int mat = v >> 9, idx = v & 511;
                int row = idx >> 2, c16 = idx & 3;
                so = sb + 16384u + (uint32_t)mat * 8192u
                   + sw64((uint32_t)(row * 64 + c16 * 16));
                gp = (mat == 0 ? Bh_ : Bl_) + (size_t)(bn + row) * D + k0 + c16 * 8;
            }
            asm volatile("cp.async.cg.shared.global [%0], [%1], 16, %2;"
                         :: "r"(so), "l"(gp), "r"(nb));
        }
        asm volatile("cp.async.commit_group;" ::: "memory");
    };

    prefetch(0);
    prefetch(1);

    const uint32_t aRB = (uint32_t)((warp_m + (lane & 15)) * 64 + (lane >> 4) * 16);
    const uint32_t bRB = (uint32_t)((warp_n + (lane & 7) + ((lane >> 4) << 3)) * 64
                                    + ((lane >> 3) & 1) * 16);

    for (int c = 0; c < NITER; c++) {
        if (c < NITER - 1) asm volatile("cp.async.wait_group 1;" ::: "memory");
        else               asm volatile("cp.async.wait_group 0;" ::: "memory");
        __syncthreads();
        if (c + 2 < NITER) prefetch(c + 2);   // writes stage (c-1)%3: consumed pre-sync

        uint32_t sb = base + (uint32_t)(c % NSTAGE) * STG_BYTES;
        #pragma unroll
        for (int ks = 0; ks < 2; ks++) {
            // liveness-ordered: bh, ah -> AhBh; al -> AlBh; bl -> AhBl
            uint32_t bh[4][2];
            #pragma unroll
            for (int n2 = 0; n2 < 2; n2++) {
                uint32_t t[4];
                ldm_x4(t, sb + 16384u + sw64(bRB + n2 * 1024 + ks * 32));
                bh[n2 * 2][0] = t[0]; bh[n2 * 2][1] = t[1];
                bh[n2 * 2 + 1][0] = t[2]; bh[n2 * 2 + 1][1] = t[3];
            }
            uint32_t ah[4][4];
            #pragma unroll
            for (int mf = 0; mf < 4; mf++)
                ldm_x4(ah[mf], sb + sw64(aRB + mf * 1024 + ks * 32));
            #pragma unroll
            for (int mf = 0; mf < 4; mf++)
                #pragma unroll
                for (int nf = 0; nf < 4; nf++)
                    mma_bf16(acc[mf][nf], ah[mf], bh[nf]);

            uint32_t al[4][4];
            #pragma unroll
            for (int mf = 0; mf < 4; mf++)
                ldm_x4(al[mf], sb + 8192u + sw64(aRB + mf * 1024 + ks * 32));
            #pragma unroll
            for (int mf = 0; mf < 4; mf++)
                #pragma unroll
                for (int nf = 0; nf < 4; nf++)
                    mma_bf16(acc[mf][nf], al[mf], bh[nf]);

            uint32_t bl[4][2];
            #pragma unroll
            for (int n2 = 0; n2 < 2; n2++) {
                uint32_t t[4];
                ldm_x4(t, sb + 24576u + sw64(bRB + n2 * 1024 + ks * 32));
                bl[n2 * 2][0] = t[0]; bl[n2 * 2][1] = t[1];
                bl[n2 * 2 + 1][0] = t[2]; bl[n2 * 2 + 1][1] = t[3];
            }
            #pragma unroll
            for (int mf = 0; mf < 4; mf++)
                #pragma unroll
                for (int nf = 0; nf < 4; nf++)
                    mma_bf16(acc[mf][nf], ah[mf], bl[nf]);
        }
    }

    // ---- epilogue -----------------------------------------------------------
    const int grp = lane >> 2, tig = lane & 3;
    #pragma unroll
    for (int mf = 0; mf < 4; mf++) {
        #pragma unroll
        for (int h2 = 0; h2 < 2; h2++) {
            int row = bm + warp_m + mf * 16 + grp + h2 * 8;
            if (row >= M) continue;
            #pragma unroll
            for (int nf = 0; nf < 4; nf++) {
                int col = bn + warp_n + nf * 8 + tig * 2;
                float v0 = acc[mf][nf][h2 * 2 + 0] + __ldg(&bias[col]);
                float v1 = acc[mf][nf][h2 * 2 + 1] + __ldg(&bias[col + 1]);
                if (EPI == 1) { v0 = fmaxf(v0, 0.f); v1 = fmaxf(v1, 0.f); }
                else if (EPI == 2) { v0 = gelu_f(v0); v1 = gelu_f(v1); }
                if (OUT == 1) {
                    bf16 h0 = __float2bfloat16_rn(v0), h1 = __float2bfloat16_rn(v1);
                    bf16 l0 = __float2bfloat16_rn(v0 - __bfloat162float(h0));
                    bf16 l1 = __float2bfloat16_rn(v1 - __bfloat162float(h1));
                    *(__nv_bfloat162*)(Ch + (size_t)row * D + col) = __halves2bfloat162(h0, h1);
                    *(__nv_bfloat162*)(Cl + (size_t)row * D + col) = __halves2bfloat162(l0, l1);
                } else {
                    *(float2*)(C + (size_t)row * D + col) = make_float2(v0, v1);
                    if (OUT == 2)
                        *(float2*)(C2 + (size_t)row * D + col) = make_float2(v0, v1);
                }
            }
        }
    }
}

// ---------------------------------------------------------------------------
// Fused embedding-sum + LayerNorm -> pre-split bf16 hi/lo.
// ids == nullptr -> synthesize ids from row index (bond table 8x8x8).
// ---------------------------------------------------------------------------
__global__ void encode_embed_ln(const int* __restrict__ ids, int F, int V,
                                const float* __restrict__ emb,
                                const float* __restrict__ g,
                                const float* __restrict__ b,
                                bf16* __restrict__ oh, bf16* __restrict__ ol, int M)
{
    int row = blockIdx.x;
    if (row >= M) return;
    __shared__ int   sid[16];
    __shared__ float sred[2][8];
    __shared__ float smv[2];
    int tid = threadIdx.x;
    if (ids) {
        if (tid < F) sid[tid] = ids[(size_t)row * F + tid];
    } else if (tid == 0) {
        sid[0] = row >> 6; sid[1] = (row >> 3) & 7; sid[2] = row & 7;
    }
    __syncthreads();

    float v[3];
    float s = 0.f, q = 0.f;
    #pragma unroll
    for (int t = 0; t < 3; t++) {
        int c = tid + t * 256;
        float acc = 0.f;
        for (int f = 0; f < F; f++)
            acc += emb[((size_t)f * V + sid[f]) * D + c];
        v[t] = acc;
        s += acc;
        q += acc * acc;
    }
    #pragma unroll
    for (int off = 16; off; off >>= 1) {
        s += __shfl_down_sync(0xffffffffu, s, off);
        q += __shfl_down_sync(0xffffffffu, q, off);
    }
    int wid = tid >> 5, lane = tid & 31;
    if (lane == 0) { sred[0][wid] = s; sred[1][wid] = q; }
    __syncthreads();
    if (tid == 0) {
        float ss = 0.f, qq = 0.f;
        #pragma unroll
        for (int i = 0; i < 8; i++) { ss += sred[0][i]; qq += sred[1][i]; }
        float mean = ss * (1.0f / D);
        float var  = qq * (1.0f / D) - mean * mean;
        smv[0] = mean;
        smv[1] = rsqrtf(var + 1e-5f);
    }
    __syncthreads();
    float mean = smv[0], rstd = smv[1];
    #pragma unroll
    for (int t = 0; t < 3; t++) {
        int c = tid + t * 256;
        float val = (v[t] - mean) * rstd * g[c] + b[c];
        bf16 h = __float2bfloat16_rn(val);
        bf16 l = __float2bfloat16_rn(val - __bfloat162float(h));
        oh[(size_t)row * D + c] = h;
        ol[(size_t)row * D + c] = l;
    }
}

// ---------------------------------------------------------------------------
// Per-edge bond type index
// ---------------------------------------------------------------------------
__global__ void etype_k(const int* __restrict__ ea, int* __restrict__ et, int E)
{
    int i = blockIdx.x * blockDim.x + threadIdx.x;
    if (i >= E) return;
    et[i] = ea[i * 3] * 64 + ea[i * 3 + 1] * 8 + ea[i * 3 + 2];
}

// ---------------------------------------------------------------------------
// z = agg (pre-initialized with h, then scatter-added), pre-split bf16 hi/lo.
// ---------------------------------------------------------------------------
__global__ void zsplit(const float* __restrict__ agg,
                       bf16* __restrict__ sh, bf16* __restrict__ sl, int total4)
{
    int i = blockIdx.x * blockDim.x + threadIdx.x;
    if (i >= total4) return;
    float4 a = *(const float4*)(agg + (size_t)i * 4);
    bf16 h0 = __float2bfloat16_rn(a.x), h1 = __float2bfloat16_rn(a.y);
    bf16 h2 = __float2bfloat16_rn(a.z), h3 = __float2bfloat16_rn(a.w);
    bf16 l0 = __float2bfloat16_rn(a.x - __bfloat162float(h0));
    bf16 l1 = __float2bfloat16_rn(a.y - __bfloat162float(h1));
    bf16 l2 = __float2bfloat16_rn(a.z - __bfloat162float(h2));
    bf16 l3 = __float2bfloat16_rn(a.w - __bfloat162float(h3));
    __nv_bfloat162 hp0 = __halves2bfloat162(h0, h1), hp1 = __halves2bfloat162(h2, h3);
    __nv_bfloat162 lp0 = __halves2bfloat162(l0, l1), lp1 = __halves2bfloat162(l2, l3);
    *(uint2*)(sh + (size_t)i * 4) = make_uint2(*(uint32_t*)&hp0, *(uint32_t*)&hp1);
    *(uint2*)(sl + (size_t)i * 4) = make_uint2(*(uint32_t*)&lp0, *(uint32_t*)&lp1);
}

// ---------------------------------------------------------------------------
// Fused gelu + residual + LayerNorm; writes h AND agg (pre-init for next layer)
// ---------------------------------------------------------------------------
__global__ void gelu_res_ln(const float* __restrict__ u, float* __restrict__ h,
                            float* __restrict__ agg,
                            const float* __restrict__ g,
                            const float* __restrict__ b, int M)
{
    int row = blockIdx.x;
    if (row >= M) return;
    __shared__ float sred[2][8];
    __shared__ float smv[2];
    int tid = threadIdx.x;

    float v[3];
    float s = 0.f, q = 0.f;
    #pragma unroll
    for (int t = 0; t < 3; t++) {
        int c = tid + t * 256;
        float val = gelu_f(u[(size_t)row * D + c]) + h[(size_t)row * D + c];
        v[t] = val;
        s += val;
        q += val * val;
    }
    #pragma unroll
    for (int off = 16; off; off >>= 1) {
        s += __shfl_down_sync(0xffffffffu, s, off);
        q += __shfl_down_sync(0xffffffffu, q, off);
    }
    int wid = tid >> 5, lane = tid & 31;
    if (lane == 0) { sred[0][wid] = s; sred[1][wid] = q; }
    __syncthreads();
    if (tid == 0) {
        float ss = 0.f, qq = 0.f;
        #pragma unroll
        for (int i = 0; i < 8; i++) { ss += sred[0][i]; qq += sred[1][i]; }
        float mean = ss * (1.0f / D);
        float var  = qq * (1.0f / D) - mean * mean;
        smv[0] = mean;
        smv[1] = rsqrtf(var + 1e-5f);
    }
    __syncthreads();
    float mean = smv[0], rstd = smv[1];
    #pragma unroll
    for (int t = 0; t < 3; t++) {
        int c = tid + t * 256;
        float val = (v[t] - mean) * rstd * g[c] + b[c];
        h[(size_t)row * D + c] = val;
        agg[(size_t)row * D + c] = val;
    }
}

// ---------------------------------------------------------------------------
// Edge message + scatter: agg += relu(h[src] + etab[etype])   (agg pre-init=h)
// ---------------------------------------------------------------------------
__global__ void edge_scatter(const float* __restrict__ h,
                             const float* __restrict__ etab,
                             const int* __restrict__ et,
                             const int* __restrict__ src,
                             const int* __restrict__ dst,
                             float* __restrict__ agg, int E)
{
    long long i = (long long)blockIdx.x * blockDim.x + threadIdx.x;
    long long total = (long long)E * (D / 4);
    if (i >= total) return;
    int eid = (int)(i / (D / 4));
    int c   = (int)(i % (D / 4)) * 4;
    int sN  = __ldg(&src[eid]);
    int dN  = __ldg(&dst[eid]);
    int ty  = __ldg(&et[eid]);
    float4 hv = *(const float4*)(h + (size_t)sN * D + c);
    float4 ev = *(const float4*)(etab + (size_t)ty * D + c);
    float m0 = fmaxf(hv.x + ev.x, 0.f);
    float m1 = fmaxf(hv.y + ev.y, 0.f);
    float m2 = fmaxf(hv.z + ev.z, 0.f);
    float m3 = fmaxf(hv.w + ev.w, 0.f);
    float* p = agg + (size_t)dN * D + c;
    asm volatile("red.global.add.v4.f32 [%0], {%1, %2, %3, %4};"
                 :: "l"(p), "f"(m0), "f"(m1), "f"(m2), "f"(m3) : "memory");
}

// ---------------------------------------------------------------------------
extern "C" void kernel_launch(void* const* d_in, const int* in_sizes, int n_in,
                              void* d_out, int out_size)
{
    const int*   x         = (const int*)d_in[0];
    const int*   edge_attr = (const int*)d_in[1];
    const int*   edge_index= (const int*)d_in[2];
    const float* atom_emb  = (const float*)d_in[3];
    const float* atom_ln_g = (const float*)d_in[4];
    const float* atom_ln_b = (const float*)d_in[5];
    const float* atom_w1   = (const float*)d_in[6];
    const float* atom_b1   = (const float*)d_in[7];
    const float* atom_w2   = (const float*)d_in[8];
    const float* atom_b2   = (const float*)d_in[9];
    const float* bond_emb  = (const float*)d_in[10];
    const float* bond_ln_g = (const float*)d_in[11];
    const float* bond_ln_b = (const float*)d_in[12];
    const float* bond_w1   = (const float*)d_in[13];
    const float* bond_b1   = (const float*)d_in[14];
    const float* bond_w2   = (const float*)d_in[15];
    const float* bond_b2   = (const float*)d_in[16];
    const float* conv_w1   = (const float*)d_in[17];
    const float* conv_b1   = (const float*)d_in[18];
    const float* conv_w2   = (const float*)d_in[19];
    const float* conv_b2   = (const float*)d_in[20];
    const float* ln_g      = (const float*)d_in[21];
    const float* ln_b      = (const float*)d_in[22];

    int N = in_sizes[0] / 9;
    int E = in_sizes[1] / 3;
    const int* src = edge_index;
    const int* dst = edge_index + E;
    float* h = (float*)d_out;

    float *etab, *u, *agg;
    int* et;
    bf16 *s0h, *s0l, *s1h, *s1l, *wthi, *wtlo;
    cudaGetSymbolAddress((void**)&etab, g_e);
    cudaGetSymbolAddress((void**)&u,    g_u);
    cudaGetSymbolAddress((void**)&agg,  g_agg);
    cudaGetSymbolAddress((void**)&et,   g_etype);
    cudaGetSymbolAddress((void**)&s0h,  g_s0h);
    cudaGetSymbolAddress((void**)&s0l,  g_s0l);
    cudaGetSymbolAddress((void**)&s1h,  g_s1h);
    cudaGetSymbolAddress((void**)&s1l,  g_s1l);
    cudaGetSymbolAddress((void**)&wthi, g_wthi);
    cudaGetSymbolAddress((void**)&wtlo, g_wtlo);

    cudaFuncSetAttribute(gemm_mma<2, 1>, cudaFuncAttributeMaxDynamicSharedMemorySize, GEMM_SMEM);
    cudaFuncSetAttribute(gemm_mma<1, 1>, cudaFuncAttributeMaxDynamicSharedMemorySize, GEMM_SMEM);
    cudaFuncSetAttribute(gemm_mma<0, 0>, cudaFuncAttributeMaxDynamicSharedMemorySize, GEMM_SMEM);
    cudaFuncSetAttribute(gemm_mma<0, 2>, cudaFuncAttributeMaxDynamicSharedMemorySize, GEMM_SMEM);

    const size_t WSZ = (size_t)D * D;

    // pre-transpose + split all 12 weight matrices
    split_transpose_w<<<dim3(24, 24, 12), dim3(32, 8)>>>(
        atom_w1, atom_w2, bond_w1, bond_w2, conv_w1, conv_w2, wthi, wtlo);
    etype_k<<<(E + 255) / 256, 256>>>(edge_attr, et, E);

    dim3 gN(6, (N + 127) / 128);
    dim3 gT(6, 4);                      // 512-row bond table

    // --- Bond-type table (512 distinct edge types) -> etab ---
    encode_embed_ln<<<512, 256>>>(nullptr, 3, 8, bond_emb, bond_ln_g, bond_ln_b, s0h, s0l, 512);
    gemm_mma<2, 1><<<gT, 256, GEMM_SMEM>>>(s0h, s0l, wthi + 2 * WSZ, wtlo + 2 * WSZ,
                                           bond_b1, nullptr, s1h, s1l, nullptr, 512);
    gemm_mma<0, 0><<<gT, 256, GEMM_SMEM>>>(s1h, s1l, wthi + 3 * WSZ, wtlo + 3 * WSZ,
                                           bond_b2, etab, nullptr, nullptr, nullptr, 512);

    // --- Atom encoder: h = gelu(LN(emb) @ w1 + b1) @ w2 + b2 ; agg = h ---
    encode_embed_ln<<<N, 256>>>(x, 9, 128, atom_emb, atom_ln_g, atom_ln_b, s0h, s0l, N);
    gemm_mma<2, 1><<<gN, 256, GEMM_SMEM>>>(s0h, s0l, wthi + 0 * WSZ, wtlo + 0 * WSZ,
                                           atom_b1, nullptr, s1h, s1l, nullptr, N);
    gemm_mma<0, 2><<<gN, 256, GEMM_SMEM>>>(s1h, s1l, wthi + 1 * WSZ, wtlo + 1 * WSZ,
                                           atom_b2, h, nullptr, nullptr, agg, N);

    // --- 4 GINE layers ---
    long long totE = (long long)E * (D / 4);
    int edgeBlocks = (int)((totE + 255) / 256);
    int total4 = N * (D / 4);
    for (int l = 0; l < 4; l++) {
        edge_scatter<<<edgeBlocks, 256>>>(h, etab, et, src, dst, agg, E);
        zsplit<<<(total4 + 255) / 256, 256>>>(agg, s0h, s0l, total4);
        gemm_mma<1, 1><<<gN, 256, GEMM_SMEM>>>(s0h, s0l, wthi + (4 + l) * WSZ, wtlo + (4 + l) * WSZ,
                                               conv_b1 + (size_t)l * D, nullptr, s1h, s1l, nullptr, N);
        gemm_mma<0, 0><<<gN, 256, GEMM_SMEM>>>(s1h, s1l, wthi + (8 + l) * WSZ, wtlo + (8 + l) * WSZ,
                                               conv_b2 + (size_t)l * D, u, nullptr, nullptr, nullptr, N);
        gelu_res_ln<<<N, 256>>>(u, h, agg, ln_g + (size_t)l * D, ln_b + (size_t)l * D, N);
    }
}